// round 15
// baseline (speedup 1.0000x reference)
#include <cuda_runtime.h>
#include <cuda_fp16.h>

#define N_NODES 50000
#define N_EDGES 800000
#define FEAT 96
#define HID_H 64
#define HID 128
#define EGROUPS (N_EDGES / 16)
#define NGRP    (N_NODES / 16)
#define NBLK 98
#define INIT_ENC 0x007FFFFFu

typedef unsigned long long u64;
typedef unsigned u32;

__device__ float    g_delta[N_NODES * 3];
__device__ float    g_xa[N_NODES * HID];
__device__ unsigned g_agg[N_NODES * FEAT];
__device__ u32      g_cnt[N_NODES];     // zero-initialized (.bss); re-zeroed by node_post
__device__ u32      g_blk[128];         // flagged block sums; zeroed by node_pre each call
__device__ int2     g_edge[N_EDGES];

__device__ __forceinline__ unsigned enc_f(float f) {
    unsigned u = __float_as_uint(f);
    return (u & 0x80000000u) ? ~u : (u | 0x80000000u);
}
__device__ __forceinline__ float dec_f(unsigned k) {
    unsigned u = (k & 0x80000000u) ? (k & 0x7FFFFFFFu) : ~k;
    return __uint_as_float(u);
}

__device__ __forceinline__ u32 smem_u32(const void* p) {
    u32 a;
    asm("{ .reg .u64 t; cvta.to.shared.u64 t, %1; cvt.u32.u64 %0, t; }" : "=r"(a) : "l"(p));
    return a;
}

__device__ __forceinline__ void ldsm_x4(u32* r, u32 addr) {
    asm volatile("ldmatrix.sync.aligned.m8n8.x4.shared.b16 {%0,%1,%2,%3}, [%4];"
        : "=r"(r[0]), "=r"(r[1]), "=r"(r[2]), "=r"(r[3]) : "r"(addr));
}
__device__ __forceinline__ void ldsm_x4_t(u32* r, u32 addr) {
    asm volatile("ldmatrix.sync.aligned.m8n8.x4.trans.shared.b16 {%0,%1,%2,%3}, [%4];"
        : "=r"(r[0]), "=r"(r[1]), "=r"(r[2]), "=r"(r[3]) : "r"(addr));
}
__device__ __forceinline__ void mma_f16(float* d, const u32* a, const u32* b) {
    asm volatile("mma.sync.aligned.m16n8k16.row.col.f32.f16.f16.f32 "
        "{%0,%1,%2,%3}, {%4,%5,%6,%7}, {%8,%9}, {%0,%1,%2,%3};"
        : "+f"(d[0]), "+f"(d[1]), "+f"(d[2]), "+f"(d[3])
        : "r"(a[0]), "r"(a[1]), "r"(a[2]), "r"(a[3]), "r"(b[0]), "r"(b[1]));
}

__device__ __forceinline__ u32 pack_f16(float a, float b) {
    __half2 h2 = __floats2half2_rn(a, b);
    return *reinterpret_cast<u32*>(&h2);
}

// -------- fused exclusive-scan with decoupled lookback (replaces scan1 + scan_bc) --------
__global__ void scan_fused_kernel() {
    __shared__ u32 s[512];
    __shared__ u32 s_off;
    int tid = threadIdx.x, b = blockIdx.x;
    int i = b * 512 + tid;
    u32 orig = (i < N_NODES) ? g_cnt[i] : 0u;

    // local inclusive scan
    s[tid] = orig;
    __syncthreads();
    for (int off = 1; off < 512; off <<= 1) {
        u32 v = (tid >= off) ? s[tid - off] : 0u;
        __syncthreads();
        s[tid] += v;
        __syncthreads();
    }
    u32 local = s[tid];
    u32 total = s[511];

    // publish flagged block total (flag = bit 31; totals < 2^31)
    if (tid == 0) {
        __threadfence();
        atomicExch(&g_blk[b], total | 0x80000000u);
    }

    // lookback: sum all predecessor block totals (spin until published)
    u32 acc = 0;
    for (int j = tid; j < b; j += 512) {
        u32 v;
        do { v = *(volatile u32*)&g_blk[j]; } while (!(v & 0x80000000u));
        acc += v & 0x7FFFFFFFu;
    }
    __syncthreads();          // s[] free for reuse
    s[tid] = acc;
    __syncthreads();
    for (int off = 256; off > 0; off >>= 1) {
        if (tid < off) s[tid] += s[tid + off];
        __syncthreads();
    }
    if (tid == 0) s_off = s[0];
    __syncthreads();

    if (i < N_NODES) g_cnt[i] = local - orig + s_off;
}

__global__ void scatter_kernel(const int* __restrict__ ei) {
    int stride = gridDim.x * blockDim.x;
    for (int e = blockIdx.x * blockDim.x + threadIdx.x; e < N_EDGES; e += stride) {
        int d = ei[N_EDGES + e];
        u32 p = atomicAdd(&g_cnt[d], 1u);
        g_edge[p] = make_int2(ei[e], d);
    }
}

// ====== kernel 1: node_pre via single-pass fp16 mma.sync + fused agg init + hist ======
#define PRE_FW0H 0                      /* 96*272 */
#define PRE_HW0H 26112                  /* 96*144 */
#define PRE_HW1  39936
#define PRE_HB0  40704
#define PRE_HB1  40960
#define PRE_FB0  40976
#define PRE_A    41488                  /* 16 warps * 3328 */
#define PRE_TOTAL 94736
#define PRE_APITCH 208

__global__ __launch_bounds__(512, 1) void node_pre_mma(
    const float* __restrict__ x,
    const float* __restrict__ h_w0, const float* __restrict__ h_b0,
    const float* __restrict__ h_w1, const float* __restrict__ h_b1,
    const float* __restrict__ f_w0, const float* __restrict__ f_b0,
    const int*   __restrict__ ei)
{
    extern __shared__ char smem[];
    u32 sb = smem_u32(smem);
    int tid = threadIdx.x, wid = tid >> 5, lane = tid & 31;

    for (int idx = tid; idx < FEAT * 64; idx += 512) {
        int k = idx >> 6, np = idx & 63;
        *(u32*)(smem + PRE_FW0H + k * 272 + np * 4) =
            pack_f16(f_w0[(3 + k) * HID + 2 * np], f_w0[(3 + k) * HID + 2 * np + 1]);
    }
    for (int idx = tid; idx < FEAT * 32; idx += 512) {
        int k = idx >> 5, np = idx & 31;
        *(u32*)(smem + PRE_HW0H + k * 144 + np * 4) =
            pack_f16(h_w0[k * HID_H + 2 * np], h_w0[k * HID_H + 2 * np + 1]);
    }
    float* s_hw1 = (float*)(smem + PRE_HW1);
    float* s_hb0 = (float*)(smem + PRE_HB0);
    float* s_hb1 = (float*)(smem + PRE_HB1);
    float* s_fb0 = (float*)(smem + PRE_FB0);
    for (int i = tid; i < HID_H * 3; i += 512) s_hw1[i] = h_w1[i];
    if (tid < HID_H) s_hb0[tid] = h_b0[tid];
    if (tid < 3)     s_hb1[tid] = h_b1[tid];
    if (tid >= 64 && tid < 64 + HID) s_fb0[tid - 64] = f_b0[tid - 64];

    // fused agg init + g_blk clear + dst histogram (hidden under tensor work)
    {
        uint4 iv = make_uint4(INIT_ENC, INIT_ENC, INIT_ENC, INIT_ENC);
        int gt = blockIdx.x * 512 + tid, tot = gridDim.x * 512;
        uint4* ap = (uint4*)g_agg;
        for (int i = gt; i < N_NODES * FEAT / 4; i += tot) ap[i] = iv;
        if (gt < 128) g_blk[gt] = 0u;
        for (int e = gt; e < N_EDGES; e += tot)
            atomicAdd(&g_cnt[ei[N_EDGES + e]], 1u);
    }
    __syncthreads();

    const u32 aB = sb + PRE_A + (u32)wid * 3328;
    char* aT = smem + PRE_A + wid * 3328;

    const int grp = lane >> 2, q4 = lane & 3;
    const u32 a_row = (u32)(lane & 15);
    const u32 a_col8 = (u32)((lane >> 4) << 3);

    for (int g = blockIdx.x * 16 + wid; g < NGRP; g += gridDim.x * 16) {
        #pragma unroll 4
        for (int ee = 0; ee < 16; ee++) {
            const float2* xr = (const float2*)(x + (long)(g * 16 + ee) * FEAT);
            {
                int jw = lane;
                float2 v = __ldg(&xr[jw]);
                *(u32*)(aT + ee * PRE_APITCH + jw * 4) = pack_f16(v.x, v.y);
            }
            if (lane < 16) {
                int jw = 32 + lane;
                float2 v = __ldg(&xr[jw]);
                *(u32*)(aT + ee * PRE_APITCH + jw * 4) = pack_f16(v.x, v.y);
            }
        }
        __syncwarp();

        #pragma unroll
        for (int half = 0; half < 2; half++) {
            float acc[8][4];
            #pragma unroll
            for (int n = 0; n < 8; n++)
                acc[n][0] = acc[n][1] = acc[n][2] = acc[n][3] = 0.f;
            #pragma unroll 2
            for (int ks = 0; ks < 6; ks++) {
                u32 k0 = (u32)ks * 16;
                u32 ah[4];
                ldsm_x4(ah, aB + a_row * PRE_APITCH + (k0 + a_col8) * 2);
                u32 brow = (k0 + a_row) * 272;
                #pragma unroll
                for (int nb = 0; nb < 4; nb++) {
                    u32 boff = brow + ((u32)(half * 64 + nb * 16) + a_col8) * 2;
                    u32 bh[4];
                    ldsm_x4_t(bh, sb + PRE_FW0H + boff);
                    mma_f16(acc[2 * nb],     ah, &bh[0]);
                    mma_f16(acc[2 * nb + 1], ah, &bh[2]);
                }
            }
            int n0 = g * 16 + grp, n1 = n0 + 8;
            #pragma unroll
            for (int n = 0; n < 8; n++) {
                int col = half * 64 + n * 8 + q4 * 2;
                float b0 = s_fb0[col], b1 = s_fb0[col + 1];
                *(float2*)(g_xa + (long)n0 * HID + col) = make_float2(acc[n][0] + b0, acc[n][1] + b1);
                *(float2*)(g_xa + (long)n1 * HID + col) = make_float2(acc[n][2] + b0, acc[n][3] + b1);
            }
        }

        {
            float acc[8][4];
            #pragma unroll
            for (int n = 0; n < 8; n++)
                acc[n][0] = acc[n][1] = acc[n][2] = acc[n][3] = 0.f;
            #pragma unroll 2
            for (int ks = 0; ks < 6; ks++) {
                u32 k0 = (u32)ks * 16;
                u32 ah[4];
                ldsm_x4(ah, aB + a_row * PRE_APITCH + (k0 + a_col8) * 2);
                u32 brow = (k0 + a_row) * 144;
                #pragma unroll
                for (int nb = 0; nb < 4; nb++) {
                    u32 boff = brow + ((u32)(nb * 16) + a_col8) * 2;
                    u32 bh[4];
                    ldsm_x4_t(bh, sb + PRE_HW0H + boff);
                    mma_f16(acc[2 * nb],     ah, &bh[0]);
                    mma_f16(acc[2 * nb + 1], ah, &bh[2]);
                }
            }
            float p[2][3] = {{0.f,0.f,0.f},{0.f,0.f,0.f}};
            #pragma unroll
            for (int n = 0; n < 8; n++) {
                int col = n * 8 + q4 * 2;
                float b0 = s_hb0[col], b1 = s_hb0[col + 1];
                float h00 = fmaxf(acc[n][0] + b0, 0.f);
                float h01 = fmaxf(acc[n][1] + b1, 0.f);
                float h10 = fmaxf(acc[n][2] + b0, 0.f);
                float h11 = fmaxf(acc[n][3] + b1, 0.f);
                #pragma unroll
                for (int c = 0; c < 3; c++) {
                    float w0 = s_hw1[col * 3 + c], w1 = s_hw1[(col + 1) * 3 + c];
                    p[0][c] = fmaf(h00, w0, fmaf(h01, w1, p[0][c]));
                    p[1][c] = fmaf(h10, w0, fmaf(h11, w1, p[1][c]));
                }
            }
            #pragma unroll
            for (int off = 1; off < 4; off <<= 1) {
                #pragma unroll
                for (int r = 0; r < 2; r++)
                    #pragma unroll
                    for (int c = 0; c < 3; c++)
                        p[r][c] += __shfl_xor_sync(0xffffffffu, p[r][c], off);
            }
            if (q4 == 0) {
                int n0 = g * 16 + grp;
                #pragma unroll
                for (int c = 0; c < 3; c++) {
                    g_delta[n0 * 3 + c]       = p[0][c] + s_hb1[c];
                    g_delta[(n0 + 8) * 3 + c] = p[1][c] + s_hb1[c];
                }
            }
        }
        __syncwarp();
    }
}

// ============ kernel 2: edge MLP — single-pass fp16, sorted + run-dedup ============
#define SM_W3   0
#define SM_SCR  1536
#define SM_BHI  6656
#define SM_D    33280
#define SM_EDGE_TOTAL 135680
#define B_PITCH 208
#define D_PITCH 100

__global__ __launch_bounds__(512, 1) void edge_mma_kernel(
    const float* __restrict__ pos,
    const float* __restrict__ f_w0,
    const float* __restrict__ f_w1)
{
    extern __shared__ char smem[];
    u32 sb = smem_u32(smem);
    int tid = threadIdx.x, wid = tid >> 5, lane = tid & 31;

    float* s_w3 = (float*)(smem + SM_W3);
    for (int i = tid; i < 3 * HID; i += 512) s_w3[i] = f_w0[i];
    for (int idx = tid; idx < HID * FEAT; idx += 512) {
        int k = idx / FEAT, n = idx % FEAT;
        *(__half*)(smem + SM_BHI + k * B_PITCH + n * 2) = __float2half(f_w1[idx]);
    }
    __syncthreads();

    float* s_rel = (float*)(smem + SM_SCR + wid * 320);
    int*   s_src = (int*)(smem + SM_SCR + wid * 320 + 192);
    int*   s_dst = (int*)(smem + SM_SCR + wid * 320 + 256);
    float* s_dt  = (float*)(smem + SM_D + wid * (16 * D_PITCH * 4));

    const int grp = lane >> 2, q4 = lane & 3;
    const u32 a_row = (u32)(lane & 15);
    const u32 a_col8 = (u32)((lane >> 4) << 3);

    for (int g = blockIdx.x * 16 + wid; g < EGROUPS; g += gridDim.x * 16) {
        if (lane < 16) {
            int2 e = g_edge[g * 16 + lane];
            s_src[lane] = e.x; s_dst[lane] = e.y;
            #pragma unroll
            for (int c = 0; c < 3; c++)
                s_rel[lane * 3 + c] = pos[e.x * 3 + c] - pos[e.y * 3 + c] + g_delta[e.y * 3 + c];
        }
        __syncwarp();

        const float* xaA = g_xa + (long)s_src[grp] * HID;
        const float* xaB = g_xa + (long)s_src[grp + 8] * HID;
        float rA0 = s_rel[grp * 3], rA1 = s_rel[grp * 3 + 1], rA2 = s_rel[grp * 3 + 2];
        float rB0 = s_rel[(grp + 8) * 3], rB1 = s_rel[(grp + 8) * 3 + 1], rB2 = s_rel[(grp + 8) * 3 + 2];

        float acc[12][4];
        #pragma unroll
        for (int n = 0; n < 12; n++)
            acc[n][0] = acc[n][1] = acc[n][2] = acc[n][3] = 0.f;

        #pragma unroll 2
        for (int ks = 0; ks < 8; ks++) {
            int c0 = ks * 16 + q4 * 2, c1 = c0 + 8;
            float2 xA0 = __ldg((const float2*)(xaA + c0));
            float2 xB0 = __ldg((const float2*)(xaB + c0));
            float2 xA1 = __ldg((const float2*)(xaA + c1));
            float2 xB1 = __ldg((const float2*)(xaB + c1));
            float2 w0a = *(const float2*)&s_w3[c0];
            float2 w1a = *(const float2*)&s_w3[HID + c0];
            float2 w2a = *(const float2*)&s_w3[2 * HID + c0];
            float2 w0b = *(const float2*)&s_w3[c1];
            float2 w1b = *(const float2*)&s_w3[HID + c1];
            float2 w2b = *(const float2*)&s_w3[2 * HID + c1];

            float hA0x = fmaxf(fmaf(rA0, w0a.x, fmaf(rA1, w1a.x, fmaf(rA2, w2a.x, xA0.x))), 0.f);
            float hA0y = fmaxf(fmaf(rA0, w0a.y, fmaf(rA1, w1a.y, fmaf(rA2, w2a.y, xA0.y))), 0.f);
            float hB0x = fmaxf(fmaf(rB0, w0a.x, fmaf(rB1, w1a.x, fmaf(rB2, w2a.x, xB0.x))), 0.f);
            float hB0y = fmaxf(fmaf(rB0, w0a.y, fmaf(rB1, w1a.y, fmaf(rB2, w2a.y, xB0.y))), 0.f);
            float hA1x = fmaxf(fmaf(rA0, w0b.x, fmaf(rA1, w1b.x, fmaf(rA2, w2b.x, xA1.x))), 0.f);
            float hA1y = fmaxf(fmaf(rA0, w0b.y, fmaf(rA1, w1b.y, fmaf(rA2, w2b.y, xA1.y))), 0.f);
            float hB1x = fmaxf(fmaf(rB0, w0b.x, fmaf(rB1, w1b.x, fmaf(rB2, w2b.x, xB1.x))), 0.f);
            float hB1y = fmaxf(fmaf(rB0, w0b.y, fmaf(rB1, w1b.y, fmaf(rB2, w2b.y, xB1.y))), 0.f);

            u32 ah[4];
            ah[0] = pack_f16(hA0x, hA0y);
            ah[1] = pack_f16(hB0x, hB0y);
            ah[2] = pack_f16(hA1x, hA1y);
            ah[3] = pack_f16(hB1x, hB1y);

            u32 brow = ((u32)ks * 16 + a_row) * B_PITCH;
            #pragma unroll
            for (int nb = 0; nb < 6; nb++) {
                u32 boff = brow + ((u32)nb * 16 + a_col8) * 2;
                u32 bh[4];
                ldsm_x4_t(bh, sb + SM_BHI + boff);
                mma_f16(acc[2 * nb],     ah, &bh[0]);
                mma_f16(acc[2 * nb + 1], ah, &bh[2]);
            }
        }

        #pragma unroll
        for (int n = 0; n < 12; n++) {
            int col = n * 8 + q4 * 2;
            *(float2*)&s_dt[grp * D_PITCH + col]       = make_float2(acc[n][0], acc[n][1]);
            *(float2*)&s_dt[(grp + 8) * D_PITCH + col] = make_float2(acc[n][2], acc[n][3]);
        }
        __syncwarp();

        {
            int cur = s_dst[0];
            float m0 = s_dt[lane], m1 = s_dt[lane + 32], m2 = s_dt[lane + 64];
            #pragma unroll
            for (int r = 1; r < 16; r++) {
                int d = s_dst[r];
                float v0 = s_dt[r * D_PITCH + lane];
                float v1 = s_dt[r * D_PITCH + lane + 32];
                float v2 = s_dt[r * D_PITCH + lane + 64];
                if (d != cur) {
                    unsigned* p = g_agg + (long)cur * FEAT;
                    atomicMax(p + lane,      enc_f(m0));
                    atomicMax(p + lane + 32, enc_f(m1));
                    atomicMax(p + lane + 64, enc_f(m2));
                    cur = d; m0 = v0; m1 = v1; m2 = v2;
                } else {
                    m0 = fmaxf(m0, v0); m1 = fmaxf(m1, v1); m2 = fmaxf(m2, v2);
                }
            }
            unsigned* p = g_agg + (long)cur * FEAT;
            atomicMax(p + lane,      enc_f(m0));
            atomicMax(p + lane + 32, enc_f(m1));
            atomicMax(p + lane + 64, enc_f(m2));
        }
        __syncwarp();
    }
}

// ============ kernel 3: node_post — single-pass fp16, 416 threads, + zero g_cnt ============
#define PO_GW0H 0
#define PO_GW1H 26112
#define PO_GB0  52736
#define PO_GB1  53248
#define PO_FB1  53632
#define PO_TOTAL 54016
#define PO_THREADS 416
#define PO_WARPS 13

__global__ __launch_bounds__(PO_THREADS, 1) void node_post_mma(
    const float* __restrict__ x,
    const float* __restrict__ g_w0, const float* __restrict__ g_b0,
    const float* __restrict__ g_w1, const float* __restrict__ g_b1,
    const float* __restrict__ f_b1,
    float* __restrict__ out)
{
    extern __shared__ char smem[];
    u32 sb = smem_u32(smem);
    int tid = threadIdx.x, wid = tid >> 5, lane = tid & 31;

    {
        int gt = blockIdx.x * PO_THREADS + tid, tot = gridDim.x * PO_THREADS;
        for (int i = gt; i < N_NODES; i += tot) g_cnt[i] = 0u;
    }

    for (int idx = tid; idx < FEAT * 64; idx += PO_THREADS) {
        int k = idx >> 6, np = idx & 63;
        *(u32*)(smem + PO_GW0H + k * 272 + np * 4) =
            pack_f16(g_w0[k * HID + 2 * np], g_w0[k * HID + 2 * np + 1]);
    }
    for (int idx = tid; idx < HID * 48; idx += PO_THREADS) {
        int k = idx / 48, np = idx % 48;
        *(u32*)(smem + PO_GW1H + k * 208 + np * 4) =
            pack_f16(g_w1[k * FEAT + 2 * np], g_w1[k * FEAT + 2 * np + 1]);
    }
    float* s_gb0 = (float*)(smem + PO_GB0);
    float* s_gb1 = (float*)(smem + PO_GB1);
    float* s_fb1 = (float*)(smem + PO_FB1);
    if (tid < HID)  s_gb0[tid] = g_b0[tid];
    if (tid >= 128 && tid < 128 + FEAT) s_gb1[tid - 128] = g_b1[tid - 128];
    if (tid >= 256 && tid < 256 + FEAT) s_fb1[tid - 256] = f_b1[tid - 256];
    __syncthreads();

    const int grp = lane >> 2, q4 = lane & 3;
    const u32 a_row = (u32)(lane & 15);
    const u32 a_col8 = (u32)((lane >> 4) << 3);

    for (int g = blockIdx.x * PO_WARPS + wid; g < NGRP; g += gridDim.x * PO_WARPS) {
        int nA = g * 16 + grp, nB = nA + 8;
        const unsigned* agA = g_agg + (long)nA * FEAT;
        const unsigned* agB = g_agg + (long)nB * FEAT;

        float acc0[8][4], acc1[8][4];
        #pragma unroll
        for (int n = 0; n < 8; n++) {
            acc0[n][0] = acc0[n][1] = acc0[n][2] = acc0[n][3] = 0.f;
            acc1[n][0] = acc1[n][1] = acc1[n][2] = acc1[n][3] = 0.f;
        }

        uint2 nA0v = __ldg((const uint2*)(agA + q4 * 2));
        uint2 nB0v = __ldg((const uint2*)(agB + q4 * 2));
        uint2 nA1v = __ldg((const uint2*)(agA + q4 * 2 + 8));
        uint2 nB1v = __ldg((const uint2*)(agB + q4 * 2 + 8));

        #pragma unroll
        for (int ks = 0; ks < 6; ks++) {
            uint2 vA0 = nA0v, vB0 = nB0v, vA1 = nA1v, vB1 = nB1v;
            if (ks < 5) {
                int c0n = (ks + 1) * 16 + q4 * 2;
                nA0v = __ldg((const uint2*)(agA + c0n));
                nB0v = __ldg((const uint2*)(agB + c0n));
                nA1v = __ldg((const uint2*)(agA + c0n + 8));
                nB1v = __ldg((const uint2*)(agB + c0n + 8));
            }
            int c0 = ks * 16 + q4 * 2, c1 = c0 + 8;
            float2 f0 = *(const float2*)&s_fb1[c0];
            float2 f1 = *(const float2*)&s_fb1[c1];
            float aA0x = (vA0.x == INIT_ENC) ? 0.f : dec_f(vA0.x) + f0.x;
            float aA0y = (vA0.y == INIT_ENC) ? 0.f : dec_f(vA0.y) + f0.y;
            float aB0x = (vB0.x == INIT_ENC) ? 0.f : dec_f(vB0.x) + f0.x;
            float aB0y = (vB0.y == INIT_ENC) ? 0.f : dec_f(vB0.y) + f0.y;
            float aA1x = (vA1.x == INIT_ENC) ? 0.f : dec_f(vA1.x) + f1.x;
            float aA1y = (vA1.y == INIT_ENC) ? 0.f : dec_f(vA1.y) + f1.y;
            float aB1x = (vB1.x == INIT_ENC) ? 0.f : dec_f(vB1.x) + f1.x;
            float aB1y = (vB1.y == INIT_ENC) ? 0.f : dec_f(vB1.y) + f1.y;

            u32 ah[4];
            ah[0] = pack_f16(aA0x, aA0y);
            ah[1] = pack_f16(aB0x, aB0y);
            ah[2] = pack_f16(aA1x, aA1y);
            ah[3] = pack_f16(aB1x, aB1y);

            u32 brow = ((u32)ks * 16 + a_row) * 272;
            #pragma unroll
            for (int nb = 0; nb < 8; nb++) {
                u32 boff = brow + ((u32)nb * 16 + a_col8) * 2;
                u32 bh[4];
                ldsm_x4_t(bh, sb + PO_GW0H + boff);
                float* a_lo2 = (nb < 4) ? acc0[2 * nb] : acc1[2 * (nb - 4)];
                float* a_hi2 = (nb < 4) ? acc0[2 * nb + 1] : acc1[2 * (nb - 4) + 1];
                mma_f16(a_lo2, ah, &bh[0]);
                mma_f16(a_hi2, ah, &bh[2]);
            }
        }

        float acc2[12][4];
        #pragma unroll
        for (int n = 0; n < 12; n++)
            acc2[n][0] = acc2[n][1] = acc2[n][2] = acc2[n][3] = 0.f;

        #pragma unroll 2
        for (int ks = 0; ks < 8; ks++) {
            int m0 = 2 * ks, m1 = 2 * ks + 1;
            const float* d0 = (m0 < 8) ? acc0[m0] : acc1[m0 - 8];
            const float* d1 = (m1 < 8) ? acc0[m1] : acc1[m1 - 8];
            int c0 = ks * 16 + q4 * 2, c1 = c0 + 8;
            float2 b0 = *(const float2*)&s_gb0[c0];
            float2 b1 = *(const float2*)&s_gb0[c1];

            u32 ah[4];
            ah[0] = pack_f16(fmaxf(d0[0] + b0.x, 0.f), fmaxf(d0[1] + b0.y, 0.f));
            ah[1] = pack_f16(fmaxf(d0[2] + b0.x, 0.f), fmaxf(d0[3] + b0.y, 0.f));
            ah[2] = pack_f16(fmaxf(d1[0] + b1.x, 0.f), fmaxf(d1[1] + b1.y, 0.f));
            ah[3] = pack_f16(fmaxf(d1[2] + b1.x, 0.f), fmaxf(d1[3] + b1.y, 0.f));

            u32 brow = ((u32)ks * 16 + a_row) * 208;
            #pragma unroll
            for (int nb = 0; nb < 6; nb++) {
                u32 boff = brow + ((u32)nb * 16 + a_col8) * 2;
                u32 bh[4];
                ldsm_x4_t(bh, sb + PO_GW1H + boff);
                mma_f16(acc2[2 * nb],     ah, &bh[0]);
                mma_f16(acc2[2 * nb + 1], ah, &bh[2]);
            }
        }

        {
            #pragma unroll
            for (int n = 0; n < 12; n++) {
                int col = n * 8 + q4 * 2;
                float b0 = s_gb1[col], b1 = s_gb1[col + 1];
                float2 x0 = *(const float2*)(x + (long)nA * FEAT + col);
                float2 x1 = *(const float2*)(x + (long)nB * FEAT + col);
                *(float2*)(out + (long)nA * FEAT + col) =
                    make_float2(x0.x + b0 + acc2[n][0], x0.y + b1 + acc2[n][1]);
                *(float2*)(out + (long)nB * FEAT + col) =
                    make_float2(x1.x + b0 + acc2[n][2], x1.y + b1 + acc2[n][3]);
            }
        }
    }
}

// ---------------- launch ----------------
extern "C" void kernel_launch(void* const* d_in, const int* in_sizes, int n_in,
                              void* d_out, int out_size)
{
    const float* x    = (const float*)d_in[0];
    const float* pos  = (const float*)d_in[1];
    const int*   ei   = (const int*)  d_in[2];
    const float* h_w0 = (const float*)d_in[3];
    const float* h_b0 = (const float*)d_in[4];
    const float* h_w1 = (const float*)d_in[5];
    const float* h_b1 = (const float*)d_in[6];
    const float* f_w0 = (const float*)d_in[7];
    const float* f_b0 = (const float*)d_in[8];
    const float* f_w1 = (const float*)d_in[9];
    const float* f_b1 = (const float*)d_in[10];
    const float* g_w0 = (const float*)d_in[11];
    const float* g_b0 = (const float*)d_in[12];
    const float* g_w1 = (const float*)d_in[13];
    const float* g_b1 = (const float*)d_in[14];
    float* out = (float*)d_out;

    cudaFuncSetAttribute(node_pre_mma,    cudaFuncAttributeMaxDynamicSharedMemorySize, PRE_TOTAL);
    cudaFuncSetAttribute(edge_mma_kernel, cudaFuncAttributeMaxDynamicSharedMemorySize, SM_EDGE_TOTAL);
    cudaFuncSetAttribute(node_post_mma,   cudaFuncAttributeMaxDynamicSharedMemorySize, PO_TOTAL);

    node_pre_mma<<<152, 512, PRE_TOTAL>>>(x, h_w0, h_b0, h_w1, h_b1, f_w0, f_b0, ei);
    scan_fused_kernel<<<NBLK, 512>>>();
    scatter_kernel<<<608, 512>>>(ei);
    edge_mma_kernel<<<152, 512, SM_EDGE_TOTAL>>>(pos, f_w0, f_w1);
    node_post_mma<<<152, PO_THREADS, PO_TOTAL>>>(x, g_w0, g_b0, g_w1, g_b1, f_b1, out);
}

// round 16
// speedup vs baseline: 1.0495x; 1.0495x over previous
#include <cuda_runtime.h>
#include <cuda_fp16.h>

#define N_NODES 50000
#define N_EDGES 800000
#define FEAT 96
#define HID_H 64
#define HID 128
#define EGROUPS (N_EDGES / 16)
#define NGRP    (N_NODES / 16)
#define NBLK 98
#define INIT_ENC 0x007FFFFFu

typedef unsigned long long u64;
typedef unsigned u32;

__device__ float    g_delta[N_NODES * 3];
__device__ float    g_xa[N_NODES * HID];
__device__ unsigned g_agg[N_NODES * FEAT];
__device__ u32      g_cnt[N_NODES];     // zero-initialized (.bss); re-zeroed by node_post
__device__ u32      g_blk[128];         // flagged block sums; zeroed by node_pre each call
__device__ int2     g_edge[N_EDGES];

__device__ __forceinline__ unsigned enc_f(float f) {
    unsigned u = __float_as_uint(f);
    return (u & 0x80000000u) ? ~u : (u | 0x80000000u);
}
__device__ __forceinline__ float dec_f(unsigned k) {
    unsigned u = (k & 0x80000000u) ? (k & 0x7FFFFFFFu) : ~k;
    return __uint_as_float(u);
}

__device__ __forceinline__ u32 smem_u32(const void* p) {
    u32 a;
    asm("{ .reg .u64 t; cvta.to.shared.u64 t, %1; cvt.u32.u64 %0, t; }" : "=r"(a) : "l"(p));
    return a;
}

__device__ __forceinline__ void ldsm_x4(u32* r, u32 addr) {
    asm volatile("ldmatrix.sync.aligned.m8n8.x4.shared.b16 {%0,%1,%2,%3}, [%4];"
        : "=r"(r[0]), "=r"(r[1]), "=r"(r[2]), "=r"(r[3]) : "r"(addr));
}
__device__ __forceinline__ void ldsm_x4_t(u32* r, u32 addr) {
    asm volatile("ldmatrix.sync.aligned.m8n8.x4.trans.shared.b16 {%0,%1,%2,%3}, [%4];"
        : "=r"(r[0]), "=r"(r[1]), "=r"(r[2]), "=r"(r[3]) : "r"(addr));
}
__device__ __forceinline__ void mma_f16(float* d, const u32* a, const u32* b) {
    asm volatile("mma.sync.aligned.m16n8k16.row.col.f32.f16.f16.f32 "
        "{%0,%1,%2,%3}, {%4,%5,%6,%7}, {%8,%9}, {%0,%1,%2,%3};"
        : "+f"(d[0]), "+f"(d[1]), "+f"(d[2]), "+f"(d[3])
        : "r"(a[0]), "r"(a[1]), "r"(a[2]), "r"(a[3]), "r"(b[0]), "r"(b[1]));
}

__device__ __forceinline__ u32 pack_f16(float a, float b) {
    __half2 h2 = __floats2half2_rn(a, b);
    return *reinterpret_cast<u32*>(&h2);
}

// -------- fused exclusive-scan with decoupled lookback --------
__global__ void scan_fused_kernel() {
    __shared__ u32 s[512];
    __shared__ u32 s_off;
    int tid = threadIdx.x, b = blockIdx.x;
    int i = b * 512 + tid;
    u32 orig = (i < N_NODES) ? g_cnt[i] : 0u;

    s[tid] = orig;
    __syncthreads();
    for (int off = 1; off < 512; off <<= 1) {
        u32 v = (tid >= off) ? s[tid - off] : 0u;
        __syncthreads();
        s[tid] += v;
        __syncthreads();
    }
    u32 local = s[tid];
    u32 total = s[511];

    if (tid == 0) {
        __threadfence();
        atomicExch(&g_blk[b], total | 0x80000000u);
    }

    u32 acc = 0;
    for (int j = tid; j < b; j += 512) {
        u32 v;
        do { v = *(volatile u32*)&g_blk[j]; } while (!(v & 0x80000000u));
        acc += v & 0x7FFFFFFFu;
    }
    __syncthreads();
    s[tid] = acc;
    __syncthreads();
    for (int off = 256; off > 0; off >>= 1) {
        if (tid < off) s[tid] += s[tid + off];
        __syncthreads();
    }
    if (tid == 0) s_off = s[0];
    __syncthreads();

    if (i < N_NODES) g_cnt[i] = local - orig + s_off;
}

__global__ void scatter_kernel(const int* __restrict__ ei) {
    int stride = gridDim.x * blockDim.x;
    for (int e = blockIdx.x * blockDim.x + threadIdx.x; e < N_EDGES; e += stride) {
        int d = ei[N_EDGES + e];
        u32 p = atomicAdd(&g_cnt[d], 1u);
        g_edge[p] = make_int2(ei[e], d);
    }
}

// ====== kernel 1: node_pre via single-pass fp16 mma.sync + fused agg init + hist ======
#define PRE_FW0H 0
#define PRE_HW0H 26112
#define PRE_HW1  39936
#define PRE_HB0  40704
#define PRE_HB1  40960
#define PRE_FB0  40976
#define PRE_A    41488
#define PRE_TOTAL 94736
#define PRE_APITCH 208

__global__ __launch_bounds__(512, 1) void node_pre_mma(
    const float* __restrict__ x,
    const float* __restrict__ h_w0, const float* __restrict__ h_b0,
    const float* __restrict__ h_w1, const float* __restrict__ h_b1,
    const float* __restrict__ f_w0, const float* __restrict__ f_b0,
    const int*   __restrict__ ei)
{
    extern __shared__ char smem[];
    u32 sb = smem_u32(smem);
    int tid = threadIdx.x, wid = tid >> 5, lane = tid & 31;

    for (int idx = tid; idx < FEAT * 64; idx += 512) {
        int k = idx >> 6, np = idx & 63;
        *(u32*)(smem + PRE_FW0H + k * 272 + np * 4) =
            pack_f16(f_w0[(3 + k) * HID + 2 * np], f_w0[(3 + k) * HID + 2 * np + 1]);
    }
    for (int idx = tid; idx < FEAT * 32; idx += 512) {
        int k = idx >> 5, np = idx & 31;
        *(u32*)(smem + PRE_HW0H + k * 144 + np * 4) =
            pack_f16(h_w0[k * HID_H + 2 * np], h_w0[k * HID_H + 2 * np + 1]);
    }
    float* s_hw1 = (float*)(smem + PRE_HW1);
    float* s_hb0 = (float*)(smem + PRE_HB0);
    float* s_hb1 = (float*)(smem + PRE_HB1);
    float* s_fb0 = (float*)(smem + PRE_FB0);
    for (int i = tid; i < HID_H * 3; i += 512) s_hw1[i] = h_w1[i];
    if (tid < HID_H) s_hb0[tid] = h_b0[tid];
    if (tid < 3)     s_hb1[tid] = h_b1[tid];
    if (tid >= 64 && tid < 64 + HID) s_fb0[tid - 64] = f_b0[tid - 64];

    {
        uint4 iv = make_uint4(INIT_ENC, INIT_ENC, INIT_ENC, INIT_ENC);
        int gt = blockIdx.x * 512 + tid, tot = gridDim.x * 512;
        uint4* ap = (uint4*)g_agg;
        for (int i = gt; i < N_NODES * FEAT / 4; i += tot) ap[i] = iv;
        if (gt < 128) g_blk[gt] = 0u;
        for (int e = gt; e < N_EDGES; e += tot)
            atomicAdd(&g_cnt[ei[N_EDGES + e]], 1u);
    }
    __syncthreads();

    const u32 aB = sb + PRE_A + (u32)wid * 3328;
    char* aT = smem + PRE_A + wid * 3328;

    const int grp = lane >> 2, q4 = lane & 3;
    const u32 a_row = (u32)(lane & 15);
    const u32 a_col8 = (u32)((lane >> 4) << 3);

    for (int g = blockIdx.x * 16 + wid; g < NGRP; g += gridDim.x * 16) {
        #pragma unroll 4
        for (int ee = 0; ee < 16; ee++) {
            const float2* xr = (const float2*)(x + (long)(g * 16 + ee) * FEAT);
            {
                int jw = lane;
                float2 v = __ldg(&xr[jw]);
                *(u32*)(aT + ee * PRE_APITCH + jw * 4) = pack_f16(v.x, v.y);
            }
            if (lane < 16) {
                int jw = 32 + lane;
                float2 v = __ldg(&xr[jw]);
                *(u32*)(aT + ee * PRE_APITCH + jw * 4) = pack_f16(v.x, v.y);
            }
        }
        __syncwarp();

        #pragma unroll
        for (int half = 0; half < 2; half++) {
            float acc[8][4];
            #pragma unroll
            for (int n = 0; n < 8; n++)
                acc[n][0] = acc[n][1] = acc[n][2] = acc[n][3] = 0.f;
            #pragma unroll 2
            for (int ks = 0; ks < 6; ks++) {
                u32 k0 = (u32)ks * 16;
                u32 ah[4];
                ldsm_x4(ah, aB + a_row * PRE_APITCH + (k0 + a_col8) * 2);
                u32 brow = (k0 + a_row) * 272;
                #pragma unroll
                for (int nb = 0; nb < 4; nb++) {
                    u32 boff = brow + ((u32)(half * 64 + nb * 16) + a_col8) * 2;
                    u32 bh[4];
                    ldsm_x4_t(bh, sb + PRE_FW0H + boff);
                    mma_f16(acc[2 * nb],     ah, &bh[0]);
                    mma_f16(acc[2 * nb + 1], ah, &bh[2]);
                }
            }
            int n0 = g * 16 + grp, n1 = n0 + 8;
            #pragma unroll
            for (int n = 0; n < 8; n++) {
                int col = half * 64 + n * 8 + q4 * 2;
                float b0 = s_fb0[col], b1 = s_fb0[col + 1];
                *(float2*)(g_xa + (long)n0 * HID + col) = make_float2(acc[n][0] + b0, acc[n][1] + b1);
                *(float2*)(g_xa + (long)n1 * HID + col) = make_float2(acc[n][2] + b0, acc[n][3] + b1);
            }
        }

        {
            float acc[8][4];
            #pragma unroll
            for (int n = 0; n < 8; n++)
                acc[n][0] = acc[n][1] = acc[n][2] = acc[n][3] = 0.f;
            #pragma unroll 2
            for (int ks = 0; ks < 6; ks++) {
                u32 k0 = (u32)ks * 16;
                u32 ah[4];
                ldsm_x4(ah, aB + a_row * PRE_APITCH + (k0 + a_col8) * 2);
                u32 brow = (k0 + a_row) * 144;
                #pragma unroll
                for (int nb = 0; nb < 4; nb++) {
                    u32 boff = brow + ((u32)(nb * 16) + a_col8) * 2;
                    u32 bh[4];
                    ldsm_x4_t(bh, sb + PRE_HW0H + boff);
                    mma_f16(acc[2 * nb],     ah, &bh[0]);
                    mma_f16(acc[2 * nb + 1], ah, &bh[2]);
                }
            }
            float p[2][3] = {{0.f,0.f,0.f},{0.f,0.f,0.f}};
            #pragma unroll
            for (int n = 0; n < 8; n++) {
                int col = n * 8 + q4 * 2;
                float b0 = s_hb0[col], b1 = s_hb0[col + 1];
                float h00 = fmaxf(acc[n][0] + b0, 0.f);
                float h01 = fmaxf(acc[n][1] + b1, 0.f);
                float h10 = fmaxf(acc[n][2] + b0, 0.f);
                float h11 = fmaxf(acc[n][3] + b1, 0.f);
                #pragma unroll
                for (int c = 0; c < 3; c++) {
                    float w0 = s_hw1[col * 3 + c], w1 = s_hw1[(col + 1) * 3 + c];
                    p[0][c] = fmaf(h00, w0, fmaf(h01, w1, p[0][c]));
                    p[1][c] = fmaf(h10, w0, fmaf(h11, w1, p[1][c]));
                }
            }
            #pragma unroll
            for (int off = 1; off < 4; off <<= 1) {
                #pragma unroll
                for (int r = 0; r < 2; r++)
                    #pragma unroll
                    for (int c = 0; c < 3; c++)
                        p[r][c] += __shfl_xor_sync(0xffffffffu, p[r][c], off);
            }
            if (q4 == 0) {
                int n0 = g * 16 + grp;
                #pragma unroll
                for (int c = 0; c < 3; c++) {
                    g_delta[n0 * 3 + c]       = p[0][c] + s_hb1[c];
                    g_delta[(n0 + 8) * 3 + c] = p[1][c] + s_hb1[c];
                }
            }
        }
        __syncwarp();
    }
}

// ============ kernel 2: edge MLP — fp16, wide xa loads + shfl A-frags ============
#define SM_W3   0
#define SM_SCR  1536
#define SM_BHI  6656
#define SM_D    33280                   /* 16 warps * 16 rows * 104 floats */
#define SM_EDGE_TOTAL 139776
#define B_PITCH 208
#define D_PITCH 104

__global__ __launch_bounds__(512, 1) void edge_mma_kernel(
    const float* __restrict__ pos,
    const float* __restrict__ f_w0,
    const float* __restrict__ f_w1)
{
    extern __shared__ char smem[];
    u32 sb = smem_u32(smem);
    int tid = threadIdx.x, wid = tid >> 5, lane = tid & 31;

    float* s_w3 = (float*)(smem + SM_W3);
    for (int i = tid; i < 3 * HID; i += 512) s_w3[i] = f_w0[i];
    for (int idx = tid; idx < HID * FEAT; idx += 512) {
        int k = idx / FEAT, n = idx % FEAT;
        *(__half*)(smem + SM_BHI + k * B_PITCH + n * 2) = __float2half(f_w1[idx]);
    }
    __syncthreads();

    float* s_rel = (float*)(smem + SM_SCR + wid * 320);
    int*   s_src = (int*)(smem + SM_SCR + wid * 320 + 192);
    int*   s_dst = (int*)(smem + SM_SCR + wid * 320 + 256);
    float* s_dt  = (float*)(smem + SM_D + wid * (16 * D_PITCH * 4));

    const int grp = lane >> 2, q4 = lane & 3;
    const u32 a_row = (u32)(lane & 15);
    const u32 a_col8 = (u32)((lane >> 4) << 3);
    const int src0 = (grp << 2) | (q4 >> 1);       // shfl source for cols 2q4,2q4+1
    const int src1 = src0 | 2;                     // shfl source for cols 8+2q4,+1
    const bool oddq = (q4 & 1);

    for (int g = blockIdx.x * 16 + wid; g < EGROUPS; g += gridDim.x * 16) {
        if (lane < 16) {
            int2 e = g_edge[g * 16 + lane];
            s_src[lane] = e.x; s_dst[lane] = e.y;
            #pragma unroll
            for (int c = 0; c < 3; c++)
                s_rel[lane * 3 + c] = pos[e.x * 3 + c] - pos[e.y * 3 + c] + g_delta[e.y * 3 + c];
        }
        __syncwarp();

        const float* xaA = g_xa + (long)s_src[grp] * HID;
        const float* xaB = g_xa + (long)s_src[grp + 8] * HID;
        float rA0 = s_rel[grp * 3], rA1 = s_rel[grp * 3 + 1], rA2 = s_rel[grp * 3 + 2];
        float rB0 = s_rel[(grp + 8) * 3], rB1 = s_rel[(grp + 8) * 3 + 1], rB2 = s_rel[(grp + 8) * 3 + 2];

        float acc[12][4];
        #pragma unroll
        for (int n = 0; n < 12; n++)
            acc[n][0] = acc[n][1] = acc[n][2] = acc[n][3] = 0.f;

        #pragma unroll 2
        for (int ks = 0; ks < 8; ks++) {
            int j0 = ks * 16 + q4 * 4;
            float4 fA = __ldg((const float4*)(xaA + j0));
            float4 fB = __ldg((const float4*)(xaB + j0));
            float4 w0 = *(const float4*)&s_w3[j0];
            float4 w1 = *(const float4*)&s_w3[HID + j0];
            float4 w2 = *(const float4*)&s_w3[2 * HID + j0];

            float hA0 = fmaxf(fmaf(rA0, w0.x, fmaf(rA1, w1.x, fmaf(rA2, w2.x, fA.x))), 0.f);
            float hA1 = fmaxf(fmaf(rA0, w0.y, fmaf(rA1, w1.y, fmaf(rA2, w2.y, fA.y))), 0.f);
            float hA2 = fmaxf(fmaf(rA0, w0.z, fmaf(rA1, w1.z, fmaf(rA2, w2.z, fA.z))), 0.f);
            float hA3 = fmaxf(fmaf(rA0, w0.w, fmaf(rA1, w1.w, fmaf(rA2, w2.w, fA.w))), 0.f);
            float hB0 = fmaxf(fmaf(rB0, w0.x, fmaf(rB1, w1.x, fmaf(rB2, w2.x, fB.x))), 0.f);
            float hB1 = fmaxf(fmaf(rB0, w0.y, fmaf(rB1, w1.y, fmaf(rB2, w2.y, fB.y))), 0.f);
            float hB2 = fmaxf(fmaf(rB0, w0.z, fmaf(rB1, w1.z, fmaf(rB2, w2.z, fB.z))), 0.f);
            float hB3 = fmaxf(fmaf(rB0, w0.w, fmaf(rB1, w1.w, fmaf(rB2, w2.w, fB.w))), 0.f);

            u32 pA0 = pack_f16(hA0, hA1), pA1 = pack_f16(hA2, hA3);
            u32 pB0 = pack_f16(hB0, hB1), pB1 = pack_f16(hB2, hB3);

            u32 ah[4];
            {
                u32 v0 = __shfl_sync(0xffffffffu, pA0, src0);
                u32 v1 = __shfl_sync(0xffffffffu, pA1, src0);
                ah[0] = oddq ? v1 : v0;
            }
            {
                u32 v0 = __shfl_sync(0xffffffffu, pB0, src0);
                u32 v1 = __shfl_sync(0xffffffffu, pB1, src0);
                ah[1] = oddq ? v1 : v0;
            }
            {
                u32 v0 = __shfl_sync(0xffffffffu, pA0, src1);
                u32 v1 = __shfl_sync(0xffffffffu, pA1, src1);
                ah[2] = oddq ? v1 : v0;
            }
            {
                u32 v0 = __shfl_sync(0xffffffffu, pB0, src1);
                u32 v1 = __shfl_sync(0xffffffffu, pB1, src1);
                ah[3] = oddq ? v1 : v0;
            }

            u32 brow = ((u32)ks * 16 + a_row) * B_PITCH;
            #pragma unroll
            for (int nb = 0; nb < 6; nb++) {
                u32 boff = brow + ((u32)nb * 16 + a_col8) * 2;
                u32 bh[4];
                ldsm_x4_t(bh, sb + SM_BHI + boff);
                mma_f16(acc[2 * nb],     ah, &bh[0]);
                mma_f16(acc[2 * nb + 1], ah, &bh[2]);
            }
        }

        // ---- dump D to per-warp smem tile (pitch 104: conflict-free STS.64) ----
        #pragma unroll
        for (int n = 0; n < 12; n++) {
            int col = n * 8 + q4 * 2;
            *(float2*)&s_dt[grp * D_PITCH + col]       = make_float2(acc[n][0], acc[n][1]);
            *(float2*)&s_dt[(grp + 8) * D_PITCH + col] = make_float2(acc[n][2], acc[n][3]);
        }
        __syncwarp();

        // ---- run-length max-scan via float2 (lane: f2-col lane; lanes<16 also +32) ----
        {
            int cur = s_dst[0];
            float2 m0 = *(const float2*)&s_dt[2 * lane];
            float2 m1 = (lane < 16) ? *(const float2*)&s_dt[64 + 2 * lane] : make_float2(0.f, 0.f);
            #pragma unroll
            for (int r = 1; r < 16; r++) {
                int d = s_dst[r];
                float2 v0 = *(const float2*)&s_dt[r * D_PITCH + 2 * lane];
                float2 v1 = (lane < 16) ? *(const float2*)&s_dt[r * D_PITCH + 64 + 2 * lane]
                                        : make_float2(0.f, 0.f);
                if (d != cur) {
                    unsigned* p = g_agg + (long)cur * FEAT;
                    atomicMax(p + 2 * lane,     enc_f(m0.x));
                    atomicMax(p + 2 * lane + 1, enc_f(m0.y));
                    if (lane < 16) {
                        atomicMax(p + 64 + 2 * lane,     enc_f(m1.x));
                        atomicMax(p + 64 + 2 * lane + 1, enc_f(m1.y));
                    }
                    cur = d; m0 = v0; m1 = v1;
                } else {
                    m0.x = fmaxf(m0.x, v0.x); m0.y = fmaxf(m0.y, v0.y);
                    m1.x = fmaxf(m1.x, v1.x); m1.y = fmaxf(m1.y, v1.y);
                }
            }
            unsigned* p = g_agg + (long)cur * FEAT;
            atomicMax(p + 2 * lane,     enc_f(m0.x));
            atomicMax(p + 2 * lane + 1, enc_f(m0.y));
            if (lane < 16) {
                atomicMax(p + 64 + 2 * lane,     enc_f(m1.x));
                atomicMax(p + 64 + 2 * lane + 1, enc_f(m1.y));
            }
        }
        __syncwarp();
    }
}

// ============ kernel 3: node_post — single-pass fp16, 384 threads, + zero g_cnt ============
#define PO_GW0H 0
#define PO_GW1H 26112
#define PO_GB0  52736
#define PO_GB1  53248
#define PO_FB1  53632
#define PO_TOTAL 54016

__global__ __launch_bounds__(384, 1) void node_post_mma(
    const float* __restrict__ x,
    const float* __restrict__ g_w0, const float* __restrict__ g_b0,
    const float* __restrict__ g_w1, const float* __restrict__ g_b1,
    const float* __restrict__ f_b1,
    float* __restrict__ out)
{
    extern __shared__ char smem[];
    u32 sb = smem_u32(smem);
    int tid = threadIdx.x, wid = tid >> 5, lane = tid & 31;

    {
        int gt = blockIdx.x * 384 + tid, tot = gridDim.x * 384;
        for (int i = gt; i < N_NODES; i += tot) g_cnt[i] = 0u;
    }

    for (int idx = tid; idx < FEAT * 64; idx += 384) {
        int k = idx >> 6, np = idx & 63;
        *(u32*)(smem + PO_GW0H + k * 272 + np * 4) =
            pack_f16(g_w0[k * HID + 2 * np], g_w0[k * HID + 2 * np + 1]);
    }
    for (int idx = tid; idx < HID * 48; idx += 384) {
        int k = idx / 48, np = idx % 48;
        *(u32*)(smem + PO_GW1H + k * 208 + np * 4) =
            pack_f16(g_w1[k * FEAT + 2 * np], g_w1[k * FEAT + 2 * np + 1]);
    }
    float* s_gb0 = (float*)(smem + PO_GB0);
    float* s_gb1 = (float*)(smem + PO_GB1);
    float* s_fb1 = (float*)(smem + PO_FB1);
    if (tid < HID)  s_gb0[tid] = g_b0[tid];
    if (tid >= 128 && tid < 128 + FEAT) s_gb1[tid - 128] = g_b1[tid - 128];
    if (tid >= 256 && tid < 256 + FEAT) s_fb1[tid - 256] = f_b1[tid - 256];
    __syncthreads();

    const int grp = lane >> 2, q4 = lane & 3;
    const u32 a_row = (u32)(lane & 15);
    const u32 a_col8 = (u32)((lane >> 4) << 3);

    for (int g = blockIdx.x * 12 + wid; g < NGRP; g += gridDim.x * 12) {
        int nA = g * 16 + grp, nB = nA + 8;
        const unsigned* agA = g_agg + (long)nA * FEAT;
        const unsigned* agB = g_agg + (long)nB * FEAT;

        float acc0[8][4], acc1[8][4];
        #pragma unroll
        for (int n = 0; n < 8; n++) {
            acc0[n][0] = acc0[n][1] = acc0[n][2] = acc0[n][3] = 0.f;
            acc1[n][0] = acc1[n][1] = acc1[n][2] = acc1[n][3] = 0.f;
        }

        uint2 nA0v = __ldg((const uint2*)(agA + q4 * 2));
        uint2 nB0v = __ldg((const uint2*)(agB + q4 * 2));
        uint2 nA1v = __ldg((const uint2*)(agA + q4 * 2 + 8));
        uint2 nB1v = __ldg((const uint2*)(agB + q4 * 2 + 8));

        #pragma unroll
        for (int ks = 0; ks < 6; ks++) {
            uint2 vA0 = nA0v, vB0 = nB0v, vA1 = nA1v, vB1 = nB1v;
            if (ks < 5) {
                int c0n = (ks + 1) * 16 + q4 * 2;
                nA0v = __ldg((const uint2*)(agA + c0n));
                nB0v = __ldg((const uint2*)(agB + c0n));
                nA1v = __ldg((const uint2*)(agA + c0n + 8));
                nB1v = __ldg((const uint2*)(agB + c0n + 8));
            }
            int c0 = ks * 16 + q4 * 2, c1 = c0 + 8;
            float2 f0 = *(const float2*)&s_fb1[c0];
            float2 f1 = *(const float2*)&s_fb1[c1];
            float aA0x = (vA0.x == INIT_ENC) ? 0.f : dec_f(vA0.x) + f0.x;
            float aA0y = (vA0.y == INIT_ENC) ? 0.f : dec_f(vA0.y) + f0.y;
            float aB0x = (vB0.x == INIT_ENC) ? 0.f : dec_f(vB0.x) + f0.x;
            float aB0y = (vB0.y == INIT_ENC) ? 0.f : dec_f(vB0.y) + f0.y;
            float aA1x = (vA1.x == INIT_ENC) ? 0.f : dec_f(vA1.x) + f1.x;
            float aA1y = (vA1.y == INIT_ENC) ? 0.f : dec_f(vA1.y) + f1.y;
            float aB1x = (vB1.x == INIT_ENC) ? 0.f : dec_f(vB1.x) + f1.x;
            float aB1y = (vB1.y == INIT_ENC) ? 0.f : dec_f(vB1.y) + f1.y;

            u32 ah[4];
            ah[0] = pack_f16(aA0x, aA0y);
            ah[1] = pack_f16(aB0x, aB0y);
            ah[2] = pack_f16(aA1x, aA1y);
            ah[3] = pack_f16(aB1x, aB1y);

            u32 brow = ((u32)ks * 16 + a_row) * 272;
            #pragma unroll
            for (int nb = 0; nb < 8; nb++) {
                u32 boff = brow + ((u32)nb * 16 + a_col8) * 2;
                u32 bh[4];
                ldsm_x4_t(bh, sb + PO_GW0H + boff);
                float* a_lo2 = (nb < 4) ? acc0[2 * nb] : acc1[2 * (nb - 4)];
                float* a_hi2 = (nb < 4) ? acc0[2 * nb + 1] : acc1[2 * (nb - 4) + 1];
                mma_f16(a_lo2, ah, &bh[0]);
                mma_f16(a_hi2, ah, &bh[2]);
            }
        }

        float acc2[12][4];
        #pragma unroll
        for (int n = 0; n < 12; n++)
            acc2[n][0] = acc2[n][1] = acc2[n][2] = acc2[n][3] = 0.f;

        #pragma unroll 2
        for (int ks = 0; ks < 8; ks++) {
            int m0 = 2 * ks, m1 = 2 * ks + 1;
            const float* d0 = (m0 < 8) ? acc0[m0] : acc1[m0 - 8];
            const float* d1 = (m1 < 8) ? acc0[m1] : acc1[m1 - 8];
            int c0 = ks * 16 + q4 * 2, c1 = c0 + 8;
            float2 b0 = *(const float2*)&s_gb0[c0];
            float2 b1 = *(const float2*)&s_gb0[c1];

            u32 ah[4];
            ah[0] = pack_f16(fmaxf(d0[0] + b0.x, 0.f), fmaxf(d0[1] + b0.y, 0.f));
            ah[1] = pack_f16(fmaxf(d0[2] + b0.x, 0.f), fmaxf(d0[3] + b0.y, 0.f));
            ah[2] = pack_f16(fmaxf(d1[0] + b1.x, 0.f), fmaxf(d1[1] + b1.y, 0.f));
            ah[3] = pack_f16(fmaxf(d1[2] + b1.x, 0.f), fmaxf(d1[3] + b1.y, 0.f));

            u32 brow = ((u32)ks * 16 + a_row) * 208;
            #pragma unroll
            for (int nb = 0; nb < 6; nb++) {
                u32 boff = brow + ((u32)nb * 16 + a_col8) * 2;
                u32 bh[4];
                ldsm_x4_t(bh, sb + PO_GW1H + boff);
                mma_f16(acc2[2 * nb],     ah, &bh[0]);
                mma_f16(acc2[2 * nb + 1], ah, &bh[2]);
            }
        }

        {
            #pragma unroll
            for (int n = 0; n < 12; n++) {
                int col = n * 8 + q4 * 2;
                float b0 = s_gb1[col], b1 = s_gb1[col + 1];
                float2 x0 = *(const float2*)(x + (long)nA * FEAT + col);
                float2 x1 = *(const float2*)(x + (long)nB * FEAT + col);
                *(float2*)(out + (long)nA * FEAT + col) =
                    make_float2(x0.x + b0 + acc2[n][0], x0.y + b1 + acc2[n][1]);
                *(float2*)(out + (long)nB * FEAT + col) =
                    make_float2(x1.x + b0 + acc2[n][2], x1.y + b1 + acc2[n][3]);
            }
        }
    }
}

// ---------------- launch ----------------
extern "C" void kernel_launch(void* const* d_in, const int* in_sizes, int n_in,
                              void* d_out, int out_size)
{
    const float* x    = (const float*)d_in[0];
    const float* pos  = (const float*)d_in[1];
    const int*   ei   = (const int*)  d_in[2];
    const float* h_w0 = (const float*)d_in[3];
    const float* h_b0 = (const float*)d_in[4];
    const float* h_w1 = (const float*)d_in[5];
    const float* h_b1 = (const float*)d_in[6];
    const float* f_w0 = (const float*)d_in[7];
    const float* f_b0 = (const float*)d_in[8];
    const float* f_w1 = (const float*)d_in[9];
    const float* f_b1 = (const float*)d_in[10];
    const float* g_w0 = (const float*)d_in[11];
    const float* g_b0 = (const float*)d_in[12];
    const float* g_w1 = (const float*)d_in[13];
    const float* g_b1 = (const float*)d_in[14];
    float* out = (float*)d_out;

    cudaFuncSetAttribute(node_pre_mma,    cudaFuncAttributeMaxDynamicSharedMemorySize, PRE_TOTAL);
    cudaFuncSetAttribute(edge_mma_kernel, cudaFuncAttributeMaxDynamicSharedMemorySize, SM_EDGE_TOTAL);
    cudaFuncSetAttribute(node_post_mma,   cudaFuncAttributeMaxDynamicSharedMemorySize, PO_TOTAL);

    node_pre_mma<<<152, 512, PRE_TOTAL>>>(x, h_w0, h_b0, h_w1, h_b1, f_w0, f_b0, ei);
    scan_fused_kernel<<<NBLK, 512>>>();
    scatter_kernel<<<608, 512>>>(ei);
    edge_mma_kernel<<<152, 512, SM_EDGE_TOTAL>>>(pos, f_w0, f_w1);
    node_post_mma<<<152, 384, PO_TOTAL>>>(x, g_w0, g_b0, g_w1, g_b1, f_b1, out);
}